// round 10
// baseline (speedup 1.0000x reference)
#include <cuda_runtime.h>
#include <cuda_fp16.h>
#include <cstdint>

// ---------------------------------------------------------------------------
// GraphConvolution: out[dst] += w_e * (X @ W)[src]
// R10: edge branch 4 kernels (scan3 + memset removed; place adds bsum inline,
//      aggregate re-zeroes counts); aggregate uses half-warp split with
//      uint4 gathers (2 edges in flight, LDG.128). GEMM fp16 mma unchanged.
// ---------------------------------------------------------------------------

#define N_NODES_MAX 100000
#define E_MAX       1600000
#define IN_F  256
#define OUT_F 128

__device__ __half g_support[(size_t)N_NODES_MAX * OUT_F];
__device__ int    g_count[N_NODES_MAX];     // zero-init; re-zeroed by aggregate
__device__ int    g_offsets[N_NODES_MAX];
__device__ int    g_bsum[1024];
__device__ uint2  g_edges[E_MAX];           // (src, w bits), dst-bucketed

// int64 edge_index <=> odd 32-bit words of the first 32 values are all zero
__device__ __forceinline__ int block_is64(const unsigned int* raw, int* sh)
{
    if (threadIdx.x == 0) {
        int is64 = 1;
        #pragma unroll
        for (int k = 1; k < 64; k += 2)
            if (raw[k] != 0u) { is64 = 0; break; }
        *sh = is64;
    }
    __syncthreads();
    return *sh;
}

// ---------------- histogram over dst (counts arrive zeroed) -------------------
__global__ void hist_kernel(const unsigned int* __restrict__ raw, int E)
{
    __shared__ int sh_is64;
    const int is64 = block_is64(raw, &sh_is64);
    int e = blockIdx.x * blockDim.x + threadIdx.x;
    if (e >= E) return;
    int d = is64 ? (int)((const long long*)raw)[e] : ((const int*)raw)[e];
    atomicAdd(&g_count[d], 1);
}

// ---------------- parallel exclusive prefix sum (2 kernels) -------------------
__global__ __launch_bounds__(1024) void scan1_kernel(int M)
{
    __shared__ int sh[1024];
    const int t = threadIdx.x;
    const int i = blockIdx.x * 1024 + t;
    int v = (i < M) ? g_count[i] : 0;
    sh[t] = v; __syncthreads();
    #pragma unroll
    for (int off = 1; off < 1024; off <<= 1) {
        int x = (t >= off) ? sh[t - off] : 0;
        __syncthreads(); sh[t] += x; __syncthreads();
    }
    if (i < M) g_offsets[i] = sh[t] - v;     // block-local exclusive
    if (t == 1023) g_bsum[blockIdx.x] = sh[1023];
}

__global__ __launch_bounds__(1024) void scan2_kernel(int nb)
{
    __shared__ int sh[1024];
    const int t = threadIdx.x;
    int v = (t < nb) ? g_bsum[t] : 0;
    sh[t] = v; __syncthreads();
    #pragma unroll
    for (int off = 1; off < 1024; off <<= 1) {
        int x = (t >= off) ? sh[t - off] : 0;
        __syncthreads(); sh[t] += x; __syncthreads();
    }
    if (t < nb) g_bsum[t] = sh[t] - v;       // exclusive block prefix
}

// ---------------- place edges into dst buckets (bsum added inline) -----------
__global__ void place_kernel(const unsigned int* __restrict__ raw,
                             const float* __restrict__ ew, int E)
{
    __shared__ int sh_is64;
    const int is64 = block_is64(raw, &sh_is64);
    int e = blockIdx.x * blockDim.x + threadIdx.x;
    if (e >= E) return;
    int d, s;
    if (is64) {
        const long long* ei = (const long long*)raw;
        d = (int)ei[e]; s = (int)ei[(size_t)E + e];
    } else {
        const int* ei = (const int*)raw;
        d = ei[e]; s = ei[(size_t)E + e];
    }
    int pos = atomicAdd(&g_offsets[d], 1) + g_bsum[d >> 10];
    g_edges[pos] = make_uint2((unsigned)s, __float_as_uint(ew[e]));
}

// ---------------- fp16 mma helper ---------------------------------------------
__device__ __forceinline__ void mma_f16(
    float& c0, float& c1, float& c2, float& c3,
    uint32_t a0, uint32_t a1, uint32_t a2, uint32_t a3,
    uint32_t b0, uint32_t b1)
{
    asm volatile(
        "mma.sync.aligned.m16n8k16.row.col.f32.f16.f16.f32 "
        "{%0,%1,%2,%3}, {%4,%5,%6,%7}, {%8,%9}, {%0,%1,%2,%3};"
        : "+f"(c0), "+f"(c1), "+f"(c2), "+f"(c3)
        : "r"(a0), "r"(a1), "r"(a2), "r"(a3), "r"(b0), "r"(b1));
}

// ---------------- GEMM 128x128 CTA tile, fp16 mma, fp32 accum -----------------
#define KC 64                 // k-chunk (halves)
#define PADH 72               // smem row stride in halves

__global__ __launch_bounds__(256) void gemm_mma_kernel(
    const float* __restrict__ X, const float* __restrict__ W,
    __half* __restrict__ S, int M)
{
    __shared__ __half As[128][PADH];
    __shared__ __half Bs[128][PADH];

    const int t    = threadIdx.x;
    const int w    = t >> 5;
    const int lane = t & 31;
    const int g    = lane >> 2;
    const int tig  = lane & 3;
    const int wm   = (w & 3) * 32;
    const int wn   = (w >> 2) * 64;
    const int m0   = blockIdx.x * 128;

    float acc[2][8][4];
    #pragma unroll
    for (int mi = 0; mi < 2; mi++)
        #pragma unroll
        for (int ni = 0; ni < 8; ni++)
            #pragma unroll
            for (int r = 0; r < 4; r++) acc[mi][ni][r] = 0.0f;

    for (int k0 = 0; k0 < IN_F; k0 += KC) {
        #pragma unroll
        for (int i = 0; i < 8; i++) {
            int idx = t + i * 256;
            int r   = idx >> 4;
            int c   = (idx & 15) * 4;
            float4 v = make_float4(0.f, 0.f, 0.f, 0.f);
            if (m0 + r < M)
                v = *reinterpret_cast<const float4*>(
                        X + (size_t)(m0 + r) * IN_F + k0 + c);
            *reinterpret_cast<__half2*>(&As[r][c])     = __floats2half2_rn(v.x, v.y);
            *reinterpret_cast<__half2*>(&As[r][c + 2]) = __floats2half2_rn(v.z, v.w);
        }
        #pragma unroll
        for (int i = 0; i < 32; i++) {
            int idx = t + i * 256;
            int k   = idx >> 7;
            int n   = idx & 127;
            Bs[n][k] = __float2half_rn(W[(size_t)(k0 + k) * OUT_F + n]);
        }
        __syncthreads();

        #pragma unroll
        for (int ks = 0; ks < KC / 16; ks++) {
            const int k = ks * 16;
            uint32_t a[2][4];
            #pragma unroll
            for (int mi = 0; mi < 2; mi++) {
                int mr = wm + mi * 16 + g;
                a[mi][0] = *reinterpret_cast<const uint32_t*>(&As[mr    ][k + tig * 2]);
                a[mi][1] = *reinterpret_cast<const uint32_t*>(&As[mr + 8][k + tig * 2]);
                a[mi][2] = *reinterpret_cast<const uint32_t*>(&As[mr    ][k + 8 + tig * 2]);
                a[mi][3] = *reinterpret_cast<const uint32_t*>(&As[mr + 8][k + 8 + tig * 2]);
            }
            uint32_t b[8][2];
            #pragma unroll
            for (int ni = 0; ni < 8; ni++) {
                int nr = wn + ni * 8 + g;
                b[ni][0] = *reinterpret_cast<const uint32_t*>(&Bs[nr][k + tig * 2]);
                b[ni][1] = *reinterpret_cast<const uint32_t*>(&Bs[nr][k + 8 + tig * 2]);
            }
            #pragma unroll
            for (int mi = 0; mi < 2; mi++)
                #pragma unroll
                for (int ni = 0; ni < 8; ni++)
                    mma_f16(acc[mi][ni][0], acc[mi][ni][1],
                            acc[mi][ni][2], acc[mi][ni][3],
                            a[mi][0], a[mi][1], a[mi][2], a[mi][3],
                            b[ni][0], b[ni][1]);
        }
        __syncthreads();
    }

    #pragma unroll
    for (int mi = 0; mi < 2; mi++) {
        int r0 = m0 + wm + mi * 16 + g;
        #pragma unroll
        for (int ni = 0; ni < 8; ni++) {
            int c = wn + ni * 8 + tig * 2;
            if (r0 < M)
                *reinterpret_cast<__half2*>(S + (size_t)r0 * OUT_F + c) =
                    __floats2half2_rn(acc[mi][ni][0], acc[mi][ni][1]);
            if (r0 + 8 < M)
                *reinterpret_cast<__half2*>(S + (size_t)(r0 + 8) * OUT_F + c) =
                    __floats2half2_rn(acc[mi][ni][2], acc[mi][ni][3]);
        }
    }
}

// ---------------- aggregation: warp/node, half-warp split, uint4 gathers ------
// Lanes 0-15 process even edges, lanes 16-31 odd edges; each lane gathers 16B
// (8 fp16 features) per edge. Final xor-16 shuffle reduce, lanes 0-15 store.
__global__ __launch_bounds__(256) void aggregate_kernel(
    const __half* __restrict__ S, float* __restrict__ out, int M)
{
    const int node = (blockIdx.x * blockDim.x + threadIdx.x) >> 5;
    const int lane = threadIdx.x & 31;
    if (node >= M) return;

    const int cnt   = g_count[node];
    const int start = g_offsets[node] + g_bsum[node >> 10] - cnt;
    if (lane == 0) g_count[node] = 0;        // restore invariant for next call

    const int sub = lane >> 4;                // 0 or 1
    const int sl  = lane & 15;                // lane within sub-warp

    float acc[8];
    #pragma unroll
    for (int i = 0; i < 8; i++) acc[i] = 0.0f;

    for (int b = 0; b < cnt; b += 32) {
        const int nb = (cnt - b < 32) ? (cnt - b) : 32;
        uint2 p = make_uint2(0u, 0u);
        if (lane < nb) p = g_edges[start + b + lane];

        int j = 0;
        // 8 edges per warp-iteration (4 per sub-warp, MLP=4)
        for (; j + 8 <= nb; j += 8) {
            uint4 r[4];
            float wq[4];
            #pragma unroll
            for (int q = 0; q < 4; q++) {
                int jj = j + 2 * q + sub;
                unsigned sj = __shfl_sync(0xffffffffu, p.x, jj);
                wq[q] = __uint_as_float(__shfl_sync(0xffffffffu, p.y, jj));
                r[q] = *reinterpret_cast<const uint4*>(
                    S + (size_t)sj * OUT_F + sl * 8);
            }
            #pragma unroll
            for (int q = 0; q < 4; q++) {
                float2 f0 = __half22float2(*reinterpret_cast<__half2*>(&r[q].x));
                float2 f1 = __half22float2(*reinterpret_cast<__half2*>(&r[q].y));
                float2 f2 = __half22float2(*reinterpret_cast<__half2*>(&r[q].z));
                float2 f3 = __half22float2(*reinterpret_cast<__half2*>(&r[q].w));
                acc[0] = fmaf(wq[q], f0.x, acc[0]);
                acc[1] = fmaf(wq[q], f0.y, acc[1]);
                acc[2] = fmaf(wq[q], f1.x, acc[2]);
                acc[3] = fmaf(wq[q], f1.y, acc[3]);
                acc[4] = fmaf(wq[q], f2.x, acc[4]);
                acc[5] = fmaf(wq[q], f2.y, acc[5]);
                acc[6] = fmaf(wq[q], f3.x, acc[6]);
                acc[7] = fmaf(wq[q], f3.y, acc[7]);
            }
        }
        // remainder, 2 edges per iteration; jj<=nb<32, p[jj>=nb]==0 => no-op
        for (; j < nb; j += 2) {
            int jj = j + sub;
            unsigned sj = __shfl_sync(0xffffffffu, p.x, jj);
            float    wj = __uint_as_float(__shfl_sync(0xffffffffu, p.y, jj));
            uint4 r = *reinterpret_cast<const uint4*>(
                S + (size_t)sj * OUT_F + sl * 8);
            float2 f0 = __half22float2(*reinterpret_cast<__half2*>(&r.x));
            float2 f1 = __half22float2(*reinterpret_cast<__half2*>(&r.y));
            float2 f2 = __half22float2(*reinterpret_cast<__half2*>(&r.z));
            float2 f3 = __half22float2(*reinterpret_cast<__half2*>(&r.w));
            acc[0] = fmaf(wj, f0.x, acc[0]);
            acc[1] = fmaf(wj, f0.y, acc[1]);
            acc[2] = fmaf(wj, f1.x, acc[2]);
            acc[3] = fmaf(wj, f1.y, acc[3]);
            acc[4] = fmaf(wj, f2.x, acc[4]);
            acc[5] = fmaf(wj, f2.y, acc[5]);
            acc[6] = fmaf(wj, f3.x, acc[6]);
            acc[7] = fmaf(wj, f3.y, acc[7]);
        }
    }

    // combine the two half-warps
    #pragma unroll
    for (int i = 0; i < 8; i++)
        acc[i] += __shfl_xor_sync(0xffffffffu, acc[i], 16);

    if (sub == 0) {
        float* o = out + (size_t)node * OUT_F + sl * 8;
        *reinterpret_cast<float4*>(o)     = make_float4(acc[0], acc[1], acc[2], acc[3]);
        *reinterpret_cast<float4*>(o + 4) = make_float4(acc[4], acc[5], acc[6], acc[7]);
    }
}

// ---------------------------------------------------------------------------
extern "C" void kernel_launch(void* const* d_in, const int* in_sizes, int n_in,
                              void* d_out, int out_size)
{
    const float*        X  = (const float*)d_in[0];
    const unsigned int* EI = (const unsigned int*)d_in[1];
    const float*        EW = (const float*)d_in[2];
    const float*        W  = (const float*)d_in[3];
    float*              O  = (float*)d_out;

    const int M = out_size / OUT_F;
    const int E = in_sizes[2];

    __half* S; cudaGetSymbolAddress((void**)&S, g_support);

    const int nb1024 = (M + 1023) / 1024;

    cudaStream_t s2;
    cudaStreamCreateWithFlags(&s2, cudaStreamNonBlocking);
    cudaEvent_t evFork, evJoin;
    cudaEventCreateWithFlags(&evFork, cudaEventDisableTiming);
    cudaEventCreateWithFlags(&evJoin, cudaEventDisableTiming);

    cudaEventRecord(evFork, 0);
    cudaStreamWaitEvent(s2, evFork, 0);

    // --- branch B (s2): edge bucketing (4 kernels) ---
    hist_kernel<<<(E + 255) / 256, 256, 0, s2>>>(EI, E);
    scan1_kernel<<<nb1024, 1024, 0, s2>>>(M);
    scan2_kernel<<<1, 1024, 0, s2>>>(nb1024);
    place_kernel<<<(E + 255) / 256, 256, 0, s2>>>(EI, EW, E);
    cudaEventRecord(evJoin, s2);

    // --- branch A (default stream): GEMM ---
    gemm_mma_kernel<<<(M + 127) / 128, 256>>>(X, W, S, M);

    // --- join, then aggregate ---
    cudaStreamWaitEvent(0, evJoin, 0);
    aggregate_kernel<<<(M * 32 + 255) / 256, 256>>>(S, O, M);

    cudaStreamDestroy(s2);
    cudaEventDestroy(evFork);
    cudaEventDestroy(evJoin);
}

// round 11
// speedup vs baseline: 1.1370x; 1.1370x over previous
#include <cuda_runtime.h>
#include <cuda_fp16.h>
#include <cstdint>

// ---------------------------------------------------------------------------
// GraphConvolution: out[dst] += w_e * (X @ W)[src]
// R11 (bisect): R10's 4-kernel edge branch + R9's proven aggregate inner loop.
// ---------------------------------------------------------------------------

#define N_NODES_MAX 100000
#define E_MAX       1600000
#define IN_F  256
#define OUT_F 128

__device__ __half g_support[(size_t)N_NODES_MAX * OUT_F];
__device__ int    g_count[N_NODES_MAX];     // zero-init; re-zeroed by aggregate
__device__ int    g_offsets[N_NODES_MAX];
__device__ int    g_bsum[1024];
__device__ uint2  g_edges[E_MAX];           // (src, w bits), dst-bucketed

// int64 edge_index <=> odd 32-bit words of the first 32 values are all zero
__device__ __forceinline__ int block_is64(const unsigned int* raw, int* sh)
{
    if (threadIdx.x == 0) {
        int is64 = 1;
        #pragma unroll
        for (int k = 1; k < 64; k += 2)
            if (raw[k] != 0u) { is64 = 0; break; }
        *sh = is64;
    }
    __syncthreads();
    return *sh;
}

// ---------------- histogram over dst (counts arrive zeroed) -------------------
__global__ void hist_kernel(const unsigned int* __restrict__ raw, int E)
{
    __shared__ int sh_is64;
    const int is64 = block_is64(raw, &sh_is64);
    int e = blockIdx.x * blockDim.x + threadIdx.x;
    if (e >= E) return;
    int d = is64 ? (int)((const long long*)raw)[e] : ((const int*)raw)[e];
    atomicAdd(&g_count[d], 1);
}

// ---------------- parallel exclusive prefix sum (2 kernels) -------------------
__global__ __launch_bounds__(1024) void scan1_kernel(int M)
{
    __shared__ int sh[1024];
    const int t = threadIdx.x;
    const int i = blockIdx.x * 1024 + t;
    int v = (i < M) ? g_count[i] : 0;
    sh[t] = v; __syncthreads();
    #pragma unroll
    for (int off = 1; off < 1024; off <<= 1) {
        int x = (t >= off) ? sh[t - off] : 0;
        __syncthreads(); sh[t] += x; __syncthreads();
    }
    if (i < M) g_offsets[i] = sh[t] - v;     // block-local exclusive
    if (t == 1023) g_bsum[blockIdx.x] = sh[1023];
}

__global__ __launch_bounds__(1024) void scan2_kernel(int nb)
{
    __shared__ int sh[1024];
    const int t = threadIdx.x;
    int v = (t < nb) ? g_bsum[t] : 0;
    sh[t] = v; __syncthreads();
    #pragma unroll
    for (int off = 1; off < 1024; off <<= 1) {
        int x = (t >= off) ? sh[t - off] : 0;
        __syncthreads(); sh[t] += x; __syncthreads();
    }
    if (t < nb) g_bsum[t] = sh[t] - v;       // exclusive block prefix
}

// ---------------- place edges into dst buckets (bsum added inline) -----------
__global__ void place_kernel(const unsigned int* __restrict__ raw,
                             const float* __restrict__ ew, int E)
{
    __shared__ int sh_is64;
    const int is64 = block_is64(raw, &sh_is64);
    int e = blockIdx.x * blockDim.x + threadIdx.x;
    if (e >= E) return;
    int d, s;
    if (is64) {
        const long long* ei = (const long long*)raw;
        d = (int)ei[e]; s = (int)ei[(size_t)E + e];
    } else {
        const int* ei = (const int*)raw;
        d = ei[e]; s = ei[(size_t)E + e];
    }
    int pos = atomicAdd(&g_offsets[d], 1) + g_bsum[d >> 10];
    g_edges[pos] = make_uint2((unsigned)s, __float_as_uint(ew[e]));
}

// ---------------- fp16 mma helper ---------------------------------------------
__device__ __forceinline__ void mma_f16(
    float& c0, float& c1, float& c2, float& c3,
    uint32_t a0, uint32_t a1, uint32_t a2, uint32_t a3,
    uint32_t b0, uint32_t b1)
{
    asm volatile(
        "mma.sync.aligned.m16n8k16.row.col.f32.f16.f16.f32 "
        "{%0,%1,%2,%3}, {%4,%5,%6,%7}, {%8,%9}, {%0,%1,%2,%3};"
        : "+f"(c0), "+f"(c1), "+f"(c2), "+f"(c3)
        : "r"(a0), "r"(a1), "r"(a2), "r"(a3), "r"(b0), "r"(b1));
}

// ---------------- GEMM 128x128 CTA tile, fp16 mma, fp32 accum -----------------
#define KC 64                 // k-chunk (halves)
#define PADH 72               // smem row stride in halves

__global__ __launch_bounds__(256) void gemm_mma_kernel(
    const float* __restrict__ X, const float* __restrict__ W,
    __half* __restrict__ S, int M)
{
    __shared__ __half As[128][PADH];
    __shared__ __half Bs[128][PADH];

    const int t    = threadIdx.x;
    const int w    = t >> 5;
    const int lane = t & 31;
    const int g    = lane >> 2;
    const int tig  = lane & 3;
    const int wm   = (w & 3) * 32;
    const int wn   = (w >> 2) * 64;
    const int m0   = blockIdx.x * 128;

    float acc[2][8][4];
    #pragma unroll
    for (int mi = 0; mi < 2; mi++)
        #pragma unroll
        for (int ni = 0; ni < 8; ni++)
            #pragma unroll
            for (int r = 0; r < 4; r++) acc[mi][ni][r] = 0.0f;

    for (int k0 = 0; k0 < IN_F; k0 += KC) {
        #pragma unroll
        for (int i = 0; i < 8; i++) {
            int idx = t + i * 256;
            int r   = idx >> 4;
            int c   = (idx & 15) * 4;
            float4 v = make_float4(0.f, 0.f, 0.f, 0.f);
            if (m0 + r < M)
                v = *reinterpret_cast<const float4*>(
                        X + (size_t)(m0 + r) * IN_F + k0 + c);
            *reinterpret_cast<__half2*>(&As[r][c])     = __floats2half2_rn(v.x, v.y);
            *reinterpret_cast<__half2*>(&As[r][c + 2]) = __floats2half2_rn(v.z, v.w);
        }
        #pragma unroll
        for (int i = 0; i < 32; i++) {
            int idx = t + i * 256;
            int k   = idx >> 7;
            int n   = idx & 127;
            Bs[n][k] = __float2half_rn(W[(size_t)(k0 + k) * OUT_F + n]);
        }
        __syncthreads();

        #pragma unroll
        for (int ks = 0; ks < KC / 16; ks++) {
            const int k = ks * 16;
            uint32_t a[2][4];
            #pragma unroll
            for (int mi = 0; mi < 2; mi++) {
                int mr = wm + mi * 16 + g;
                a[mi][0] = *reinterpret_cast<const uint32_t*>(&As[mr    ][k + tig * 2]);
                a[mi][1] = *reinterpret_cast<const uint32_t*>(&As[mr + 8][k + tig * 2]);
                a[mi][2] = *reinterpret_cast<const uint32_t*>(&As[mr    ][k + 8 + tig * 2]);
                a[mi][3] = *reinterpret_cast<const uint32_t*>(&As[mr + 8][k + 8 + tig * 2]);
            }
            uint32_t b[8][2];
            #pragma unroll
            for (int ni = 0; ni < 8; ni++) {
                int nr = wn + ni * 8 + g;
                b[ni][0] = *reinterpret_cast<const uint32_t*>(&Bs[nr][k + tig * 2]);
                b[ni][1] = *reinterpret_cast<const uint32_t*>(&Bs[nr][k + 8 + tig * 2]);
            }
            #pragma unroll
            for (int mi = 0; mi < 2; mi++)
                #pragma unroll
                for (int ni = 0; ni < 8; ni++)
                    mma_f16(acc[mi][ni][0], acc[mi][ni][1],
                            acc[mi][ni][2], acc[mi][ni][3],
                            a[mi][0], a[mi][1], a[mi][2], a[mi][3],
                            b[ni][0], b[ni][1]);
        }
        __syncthreads();
    }

    #pragma unroll
    for (int mi = 0; mi < 2; mi++) {
        int r0 = m0 + wm + mi * 16 + g;
        #pragma unroll
        for (int ni = 0; ni < 8; ni++) {
            int c = wn + ni * 8 + tig * 2;
            if (r0 < M)
                *reinterpret_cast<__half2*>(S + (size_t)r0 * OUT_F + c) =
                    __floats2half2_rn(acc[mi][ni][0], acc[mi][ni][1]);
            if (r0 + 8 < M)
                *reinterpret_cast<__half2*>(S + (size_t)(r0 + 8) * OUT_F + c) =
                    __floats2half2_rn(acc[mi][ni][2], acc[mi][ni][3]);
        }
    }
}

// ---------------- warp-per-node aggregation (R9 inner loop) -------------------
__global__ __launch_bounds__(256) void aggregate_kernel(
    const __half* __restrict__ S, float* __restrict__ out, int M)
{
    const int node = (blockIdx.x * blockDim.x + threadIdx.x) >> 5;
    const int lane = threadIdx.x & 31;
    if (node >= M) return;

    const int cnt   = g_count[node];
    const int start = g_offsets[node] + g_bsum[node >> 10] - cnt;
    if (lane == 0) g_count[node] = 0;     // restore invariant for next call

    float4 acc0 = make_float4(0.f, 0.f, 0.f, 0.f);
    float4 acc1 = make_float4(0.f, 0.f, 0.f, 0.f);

    for (int b = 0; b < cnt; b += 32) {
        const int nb = (cnt - b < 32) ? (cnt - b) : 32;
        uint2 p = make_uint2(0u, 0u);
        if (lane < nb) p = g_edges[start + b + lane];

        int j = 0;
        for (; j + 4 <= nb; j += 4) {
            unsigned s0 = __shfl_sync(0xffffffffu, p.x, j);
            unsigned s1 = __shfl_sync(0xffffffffu, p.x, j + 1);
            unsigned s2 = __shfl_sync(0xffffffffu, p.x, j + 2);
            unsigned s3 = __shfl_sync(0xffffffffu, p.x, j + 3);
            float w0 = __uint_as_float(__shfl_sync(0xffffffffu, p.y, j));
            float w1 = __uint_as_float(__shfl_sync(0xffffffffu, p.y, j + 1));
            float w2 = __uint_as_float(__shfl_sync(0xffffffffu, p.y, j + 2));
            float w3 = __uint_as_float(__shfl_sync(0xffffffffu, p.y, j + 3));

            uint2 r0 = *reinterpret_cast<const uint2*>(S + (size_t)s0 * OUT_F + lane * 4);
            uint2 r1 = *reinterpret_cast<const uint2*>(S + (size_t)s1 * OUT_F + lane * 4);
            uint2 r2 = *reinterpret_cast<const uint2*>(S + (size_t)s2 * OUT_F + lane * 4);
            uint2 r3 = *reinterpret_cast<const uint2*>(S + (size_t)s3 * OUT_F + lane * 4);

            float2 a, bb;
            a  = __half22float2(*reinterpret_cast<__half2*>(&r0.x));
            bb = __half22float2(*reinterpret_cast<__half2*>(&r0.y));
            acc0.x = fmaf(w0, a.x,  acc0.x); acc0.y = fmaf(w0, a.y,  acc0.y);
            acc0.z = fmaf(w0, bb.x, acc0.z); acc0.w = fmaf(w0, bb.y, acc0.w);
            a  = __half22float2(*reinterpret_cast<__half2*>(&r1.x));
            bb = __half22float2(*reinterpret_cast<__half2*>(&r1.y));
            acc1.x = fmaf(w1, a.x,  acc1.x); acc1.y = fmaf(w1, a.y,  acc1.y);
            acc1.z = fmaf(w1, bb.x, acc1.z); acc1.w = fmaf(w1, bb.y, acc1.w);
            a  = __half22float2(*reinterpret_cast<__half2*>(&r2.x));
            bb = __half22float2(*reinterpret_cast<__half2*>(&r2.y));
            acc0.x = fmaf(w2, a.x,  acc0.x); acc0.y = fmaf(w2, a.y,  acc0.y);
            acc0.z = fmaf(w2, bb.x, acc0.z); acc0.w = fmaf(w2, bb.y, acc0.w);
            a  = __half22float2(*reinterpret_cast<__half2*>(&r3.x));
            bb = __half22float2(*reinterpret_cast<__half2*>(&r3.y));
            acc1.x = fmaf(w3, a.x,  acc1.x); acc1.y = fmaf(w3, a.y,  acc1.y);
            acc1.z = fmaf(w3, bb.x, acc1.z); acc1.w = fmaf(w3, bb.y, acc1.w);
        }
        for (; j < nb; j++) {
            unsigned sj = __shfl_sync(0xffffffffu, p.x, j);
            float    wj = __uint_as_float(__shfl_sync(0xffffffffu, p.y, j));
            uint2 r = *reinterpret_cast<const uint2*>(S + (size_t)sj * OUT_F + lane * 4);
            float2 a  = __half22float2(*reinterpret_cast<__half2*>(&r.x));
            float2 bb = __half22float2(*reinterpret_cast<__half2*>(&r.y));
            acc0.x = fmaf(wj, a.x,  acc0.x); acc0.y = fmaf(wj, a.y,  acc0.y);
            acc0.z = fmaf(wj, bb.x, acc0.z); acc0.w = fmaf(wj, bb.y, acc0.w);
        }
    }
    float4 r = make_float4(acc0.x + acc1.x, acc0.y + acc1.y,
                           acc0.z + acc1.z, acc0.w + acc1.w);
    *reinterpret_cast<float4*>(out + (size_t)node * OUT_F + lane * 4) = r;
}

// ---------------------------------------------------------------------------
extern "C" void kernel_launch(void* const* d_in, const int* in_sizes, int n_in,
                              void* d_out, int out_size)
{
    const float*        X  = (const float*)d_in[0];
    const unsigned int* EI = (const unsigned int*)d_in[1];
    const float*        EW = (const float*)d_in[2];
    const float*        W  = (const float*)d_in[3];
    float*              O  = (float*)d_out;

    const int M = out_size / OUT_F;
    const int E = in_sizes[2];

    __half* S; cudaGetSymbolAddress((void**)&S, g_support);

    const int nb1024 = (M + 1023) / 1024;

    cudaStream_t s2;
    cudaStreamCreateWithFlags(&s2, cudaStreamNonBlocking);
    cudaEvent_t evFork, evJoin;
    cudaEventCreateWithFlags(&evFork, cudaEventDisableTiming);
    cudaEventCreateWithFlags(&evJoin, cudaEventDisableTiming);

    cudaEventRecord(evFork, 0);
    cudaStreamWaitEvent(s2, evFork, 0);

    // --- branch B (s2): edge bucketing (4 kernels) ---
    hist_kernel<<<(E + 255) / 256, 256, 0, s2>>>(EI, E);
    scan1_kernel<<<nb1024, 1024, 0, s2>>>(M);
    scan2_kernel<<<1, 1024, 0, s2>>>(nb1024);
    place_kernel<<<(E + 255) / 256, 256, 0, s2>>>(EI, EW, E);
    cudaEventRecord(evJoin, s2);

    // --- branch A (default stream): GEMM ---
    gemm_mma_kernel<<<(M + 127) / 128, 256>>>(X, W, S, M);

    // --- join, then aggregate ---
    cudaStreamWaitEvent(0, evJoin, 0);
    aggregate_kernel<<<(M * 32 + 255) / 256, 256>>>(S, O, M);

    cudaStreamDestroy(s2);
    cudaEventDestroy(evFork);
    cudaEventDestroy(evJoin);
}

// round 12
// speedup vs baseline: 1.5901x; 1.3985x over previous
#include <cuda_runtime.h>
#include <cuda_fp16.h>
#include <cstdint>

// ---------------------------------------------------------------------------
// GraphConvolution: out[dst] += w_e * (X @ W)[src]
// R12: exact R9 topology (memset + 3-kernel scan + cursor + R9 aggregate),
//      single change: aggregate main loop unroll-8 (MLP 4 -> 8).
// ---------------------------------------------------------------------------

#define N_NODES_MAX 100000
#define E_MAX       1600000
#define IN_F  256
#define OUT_F 128

__device__ __half g_support[(size_t)N_NODES_MAX * OUT_F];
__device__ int    g_count[N_NODES_MAX];
__device__ int    g_offsets[N_NODES_MAX];
__device__ int    g_cursor[N_NODES_MAX];
__device__ int    g_bsum[1024];
__device__ uint2  g_edges[E_MAX];           // (src, w bits), dst-bucketed

// int64 edge_index <=> odd 32-bit words of the first 32 values are all zero
__device__ __forceinline__ int block_is64(const unsigned int* raw, int* sh)
{
    if (threadIdx.x == 0) {
        int is64 = 1;
        #pragma unroll
        for (int k = 1; k < 64; k += 2)
            if (raw[k] != 0u) { is64 = 0; break; }
        *sh = is64;
    }
    __syncthreads();
    return *sh;
}

// ---------------- histogram over dst ------------------------------------------
__global__ void hist_kernel(const unsigned int* __restrict__ raw, int E)
{
    __shared__ int sh_is64;
    const int is64 = block_is64(raw, &sh_is64);
    int e = blockIdx.x * blockDim.x + threadIdx.x;
    if (e >= E) return;
    int d = is64 ? (int)((const long long*)raw)[e] : ((const int*)raw)[e];
    atomicAdd(&g_count[d], 1);
}

// ---------------- parallel exclusive prefix sum (3 kernels) -------------------
__global__ __launch_bounds__(1024) void scan1_kernel(int M)
{
    __shared__ int sh[1024];
    const int t = threadIdx.x;
    const int i = blockIdx.x * 1024 + t;
    int v = (i < M) ? g_count[i] : 0;
    sh[t] = v; __syncthreads();
    #pragma unroll
    for (int off = 1; off < 1024; off <<= 1) {
        int x = (t >= off) ? sh[t - off] : 0;
        __syncthreads(); sh[t] += x; __syncthreads();
    }
    if (i < M) g_offsets[i] = sh[t] - v;
    if (t == 1023) g_bsum[blockIdx.x] = sh[1023];
}

__global__ __launch_bounds__(1024) void scan2_kernel(int nb)
{
    __shared__ int sh[1024];
    const int t = threadIdx.x;
    int v = (t < nb) ? g_bsum[t] : 0;
    sh[t] = v; __syncthreads();
    #pragma unroll
    for (int off = 1; off < 1024; off <<= 1) {
        int x = (t >= off) ? sh[t - off] : 0;
        __syncthreads(); sh[t] += x; __syncthreads();
    }
    if (t < nb) g_bsum[t] = sh[t] - v;
}

__global__ void scan3_kernel(int M)
{
    int i = blockIdx.x * blockDim.x + threadIdx.x;
    if (i >= M) return;
    int o = g_offsets[i] + g_bsum[i >> 10];
    g_offsets[i] = o;
    g_cursor[i]  = o;
}

// ---------------- place edges into dst buckets --------------------------------
__global__ void place_kernel(const unsigned int* __restrict__ raw,
                             const float* __restrict__ ew, int E)
{
    __shared__ int sh_is64;
    const int is64 = block_is64(raw, &sh_is64);
    int e = blockIdx.x * blockDim.x + threadIdx.x;
    if (e >= E) return;
    int d, s;
    if (is64) {
        const long long* ei = (const long long*)raw;
        d = (int)ei[e]; s = (int)ei[(size_t)E + e];
    } else {
        const int* ei = (const int*)raw;
        d = ei[e]; s = ei[(size_t)E + e];
    }
    int pos = atomicAdd(&g_cursor[d], 1);
    g_edges[pos] = make_uint2((unsigned)s, __float_as_uint(ew[e]));
}

// ---------------- fp16 mma helper ---------------------------------------------
__device__ __forceinline__ void mma_f16(
    float& c0, float& c1, float& c2, float& c3,
    uint32_t a0, uint32_t a1, uint32_t a2, uint32_t a3,
    uint32_t b0, uint32_t b1)
{
    asm volatile(
        "mma.sync.aligned.m16n8k16.row.col.f32.f16.f16.f32 "
        "{%0,%1,%2,%3}, {%4,%5,%6,%7}, {%8,%9}, {%0,%1,%2,%3};"
        : "+f"(c0), "+f"(c1), "+f"(c2), "+f"(c3)
        : "r"(a0), "r"(a1), "r"(a2), "r"(a3), "r"(b0), "r"(b1));
}

// ---------------- GEMM 128x128 CTA tile, fp16 mma, fp32 accum -----------------
#define KC 64                 // k-chunk (halves)
#define PADH 72               // smem row stride in halves

__global__ __launch_bounds__(256) void gemm_mma_kernel(
    const float* __restrict__ X, const float* __restrict__ W,
    __half* __restrict__ S, int M)
{
    __shared__ __half As[128][PADH];
    __shared__ __half Bs[128][PADH];

    const int t    = threadIdx.x;
    const int w    = t >> 5;
    const int lane = t & 31;
    const int g    = lane >> 2;
    const int tig  = lane & 3;
    const int wm   = (w & 3) * 32;
    const int wn   = (w >> 2) * 64;
    const int m0   = blockIdx.x * 128;

    float acc[2][8][4];
    #pragma unroll
    for (int mi = 0; mi < 2; mi++)
        #pragma unroll
        for (int ni = 0; ni < 8; ni++)
            #pragma unroll
            for (int r = 0; r < 4; r++) acc[mi][ni][r] = 0.0f;

    for (int k0 = 0; k0 < IN_F; k0 += KC) {
        #pragma unroll
        for (int i = 0; i < 8; i++) {
            int idx = t + i * 256;
            int r   = idx >> 4;
            int c   = (idx & 15) * 4;
            float4 v = make_float4(0.f, 0.f, 0.f, 0.f);
            if (m0 + r < M)
                v = *reinterpret_cast<const float4*>(
                        X + (size_t)(m0 + r) * IN_F + k0 + c);
            *reinterpret_cast<__half2*>(&As[r][c])     = __floats2half2_rn(v.x, v.y);
            *reinterpret_cast<__half2*>(&As[r][c + 2]) = __floats2half2_rn(v.z, v.w);
        }
        #pragma unroll
        for (int i = 0; i < 32; i++) {
            int idx = t + i * 256;
            int k   = idx >> 7;
            int n   = idx & 127;
            Bs[n][k] = __float2half_rn(W[(size_t)(k0 + k) * OUT_F + n]);
        }
        __syncthreads();

        #pragma unroll
        for (int ks = 0; ks < KC / 16; ks++) {
            const int k = ks * 16;
            uint32_t a[2][4];
            #pragma unroll
            for (int mi = 0; mi < 2; mi++) {
                int mr = wm + mi * 16 + g;
                a[mi][0] = *reinterpret_cast<const uint32_t*>(&As[mr    ][k + tig * 2]);
                a[mi][1] = *reinterpret_cast<const uint32_t*>(&As[mr + 8][k + tig * 2]);
                a[mi][2] = *reinterpret_cast<const uint32_t*>(&As[mr    ][k + 8 + tig * 2]);
                a[mi][3] = *reinterpret_cast<const uint32_t*>(&As[mr + 8][k + 8 + tig * 2]);
            }
            uint32_t b[8][2];
            #pragma unroll
            for (int ni = 0; ni < 8; ni++) {
                int nr = wn + ni * 8 + g;
                b[ni][0] = *reinterpret_cast<const uint32_t*>(&Bs[nr][k + tig * 2]);
                b[ni][1] = *reinterpret_cast<const uint32_t*>(&Bs[nr][k + 8 + tig * 2]);
            }
            #pragma unroll
            for (int mi = 0; mi < 2; mi++)
                #pragma unroll
                for (int ni = 0; ni < 8; ni++)
                    mma_f16(acc[mi][ni][0], acc[mi][ni][1],
                            acc[mi][ni][2], acc[mi][ni][3],
                            a[mi][0], a[mi][1], a[mi][2], a[mi][3],
                            b[ni][0], b[ni][1]);
        }
        __syncthreads();
    }

    #pragma unroll
    for (int mi = 0; mi < 2; mi++) {
        int r0 = m0 + wm + mi * 16 + g;
        #pragma unroll
        for (int ni = 0; ni < 8; ni++) {
            int c = wn + ni * 8 + tig * 2;
            if (r0 < M)
                *reinterpret_cast<__half2*>(S + (size_t)r0 * OUT_F + c) =
                    __floats2half2_rn(acc[mi][ni][0], acc[mi][ni][1]);
            if (r0 + 8 < M)
                *reinterpret_cast<__half2*>(S + (size_t)(r0 + 8) * OUT_F + c) =
                    __floats2half2_rn(acc[mi][ni][2], acc[mi][ni][3]);
        }
    }
}

// ---------------- warp-per-node aggregation (unroll-8 gathers) ----------------
__global__ __launch_bounds__(256) void aggregate_kernel(
    const __half* __restrict__ S, float* __restrict__ out, int M)
{
    const int node = (blockIdx.x * blockDim.x + threadIdx.x) >> 5;
    const int lane = threadIdx.x & 31;
    if (node >= M) return;

    const int start = g_offsets[node];
    const int cnt   = g_count[node];

    float4 acc0 = make_float4(0.f, 0.f, 0.f, 0.f);
    float4 acc1 = make_float4(0.f, 0.f, 0.f, 0.f);

    for (int b = 0; b < cnt; b += 32) {
        const int nb = (cnt - b < 32) ? (cnt - b) : 32;
        uint2 p = make_uint2(0u, 0u);
        if (lane < nb) p = g_edges[start + b + lane];

        int j = 0;
        // main body: 8 independent gathers in flight (MLP=8)
        for (; j + 8 <= nb; j += 8) {
            unsigned ss[8];
            float    ww[8];
            #pragma unroll
            for (int q = 0; q < 8; q++) {
                ss[q] = __shfl_sync(0xffffffffu, p.x, j + q);
                ww[q] = __uint_as_float(__shfl_sync(0xffffffffu, p.y, j + q));
            }
            uint2 rr[8];
            #pragma unroll
            for (int q = 0; q < 8; q++)
                rr[q] = *reinterpret_cast<const uint2*>(
                    S + (size_t)ss[q] * OUT_F + lane * 4);
            #pragma unroll
            for (int q = 0; q < 8; q++) {
                float2 a  = __half22float2(*reinterpret_cast<__half2*>(&rr[q].x));
                float2 bb = __half22float2(*reinterpret_cast<__half2*>(&rr[q].y));
                if (q & 1) {
                    acc1.x = fmaf(ww[q], a.x,  acc1.x);
                    acc1.y = fmaf(ww[q], a.y,  acc1.y);
                    acc1.z = fmaf(ww[q], bb.x, acc1.z);
                    acc1.w = fmaf(ww[q], bb.y, acc1.w);
                } else {
                    acc0.x = fmaf(ww[q], a.x,  acc0.x);
                    acc0.y = fmaf(ww[q], a.y,  acc0.y);
                    acc0.z = fmaf(ww[q], bb.x, acc0.z);
                    acc0.w = fmaf(ww[q], bb.y, acc0.w);
                }
            }
        }
        // remainder: 4 at a time
        for (; j + 4 <= nb; j += 4) {
            unsigned s0 = __shfl_sync(0xffffffffu, p.x, j);
            unsigned s1 = __shfl_sync(0xffffffffu, p.x, j + 1);
            unsigned s2 = __shfl_sync(0xffffffffu, p.x, j + 2);
            unsigned s3 = __shfl_sync(0xffffffffu, p.x, j + 3);
            float w0 = __uint_as_float(__shfl_sync(0xffffffffu, p.y, j));
            float w1 = __uint_as_float(__shfl_sync(0xffffffffu, p.y, j + 1));
            float w2 = __uint_as_float(__shfl_sync(0xffffffffu, p.y, j + 2));
            float w3 = __uint_as_float(__shfl_sync(0xffffffffu, p.y, j + 3));

            uint2 r0 = *reinterpret_cast<const uint2*>(S + (size_t)s0 * OUT_F + lane * 4);
            uint2 r1 = *reinterpret_cast<const uint2*>(S + (size_t)s1 * OUT_F + lane * 4);
            uint2 r2 = *reinterpret_cast<const uint2*>(S + (size_t)s2 * OUT_F + lane * 4);
            uint2 r3 = *reinterpret_cast<const uint2*>(S + (size_t)s3 * OUT_F + lane * 4);

            float2 a, bb;
            a  = __half22float2(*reinterpret_cast<__half2*>(&r0.x));
            bb = __half22float2(*reinterpret_cast<__half2*>(&r0.y));
            acc0.x = fmaf(w0, a.x,  acc0.x); acc0.y = fmaf(w0, a.y,  acc0.y);
            acc0.z = fmaf(w0, bb.x, acc0.z); acc0.w = fmaf(w0, bb.y, acc0.w);
            a  = __half22float2(*reinterpret_cast<__half2*>(&r1.x));
            bb = __half22float2(*reinterpret_cast<__half2*>(&r1.y));
            acc1.x = fmaf(w1, a.x,  acc1.x); acc1.y = fmaf(w1, a.y,  acc1.y);
            acc1.z = fmaf(w1, bb.x, acc1.z); acc1.w = fmaf(w1, bb.y, acc1.w);
            a  = __half22float2(*reinterpret_cast<__half2*>(&r2.x));
            bb = __half22float2(*reinterpret_cast<__half2*>(&r2.y));
            acc0.x = fmaf(w2, a.x,  acc0.x); acc0.y = fmaf(w2, a.y,  acc0.y);
            acc0.z = fmaf(w2, bb.x, acc0.z); acc0.w = fmaf(w2, bb.y, acc0.w);
            a  = __half22float2(*reinterpret_cast<__half2*>(&r3.x));
            bb = __half22float2(*reinterpret_cast<__half2*>(&r3.y));
            acc1.x = fmaf(w3, a.x,  acc1.x); acc1.y = fmaf(w3, a.y,  acc1.y);
            acc1.z = fmaf(w3, bb.x, acc1.z); acc1.w = fmaf(w3, bb.y, acc1.w);
        }
        for (; j < nb; j++) {
            unsigned sj = __shfl_sync(0xffffffffu, p.x, j);
            float    wj = __uint_as_float(__shfl_sync(0xffffffffu, p.y, j));
            uint2 r = *reinterpret_cast<const uint2*>(S + (size_t)sj * OUT_F + lane * 4);
            float2 a  = __half22float2(*reinterpret_cast<__half2*>(&r.x));
            float2 bb = __half22float2(*reinterpret_cast<__half2*>(&r.y));
            acc0.x = fmaf(wj, a.x,  acc0.x); acc0.y = fmaf(wj, a.y,  acc0.y);
            acc0.z = fmaf(wj, bb.x, acc0.z); acc0.w = fmaf(wj, bb.y, acc0.w);
        }
    }
    float4 r = make_float4(acc0.x + acc1.x, acc0.y + acc1.y,
                           acc0.z + acc1.z, acc0.w + acc1.w);
    *reinterpret_cast<float4*>(out + (size_t)node * OUT_F + lane * 4) = r;
}

// ---------------------------------------------------------------------------
extern "C" void kernel_launch(void* const* d_in, const int* in_sizes, int n_in,
                              void* d_out, int out_size)
{
    const float*        X  = (const float*)d_in[0];
    const unsigned int* EI = (const unsigned int*)d_in[1];
    const float*        EW = (const float*)d_in[2];
    const float*        W  = (const float*)d_in[3];
    float*              O  = (float*)d_out;

    const int M = out_size / OUT_F;
    const int E = in_sizes[2];

    __half* S;  cudaGetSymbolAddress((void**)&S, g_support);
    int*   CNT; cudaGetSymbolAddress((void**)&CNT, g_count);

    const int nb1024 = (M + 1023) / 1024;

    cudaStream_t s2;
    cudaStreamCreateWithFlags(&s2, cudaStreamNonBlocking);
    cudaEvent_t evFork, evJoin;
    cudaEventCreateWithFlags(&evFork, cudaEventDisableTiming);
    cudaEventCreateWithFlags(&evJoin, cudaEventDisableTiming);

    cudaEventRecord(evFork, 0);
    cudaStreamWaitEvent(s2, evFork, 0);

    // --- branch B (s2): edge bucketing ---
    cudaMemsetAsync(CNT, 0, (size_t)M * sizeof(int), s2);
    hist_kernel<<<(E + 255) / 256, 256, 0, s2>>>(EI, E);
    scan1_kernel<<<nb1024, 1024, 0, s2>>>(M);
    scan2_kernel<<<1, 1024, 0, s2>>>(nb1024);
    scan3_kernel<<<(M + 255) / 256, 256, 0, s2>>>(M);
    place_kernel<<<(E + 255) / 256, 256, 0, s2>>>(EI, EW, E);
    cudaEventRecord(evJoin, s2);

    // --- branch A (default stream): GEMM ---
    gemm_mma_kernel<<<(M + 127) / 128, 256>>>(X, W, S, M);

    // --- join, then aggregate ---
    cudaStreamWaitEvent(0, evJoin, 0);
    aggregate_kernel<<<(M * 32 + 255) / 256, 256>>>(S, O, M);

    cudaStreamDestroy(s2);
    cudaEventDestroy(evFork);
    cudaEventDestroy(evJoin);
}

// round 13
// speedup vs baseline: 1.6719x; 1.0514x over previous
#include <cuda_runtime.h>
#include <cuda_fp16.h>
#include <cstdint>

// ---------------------------------------------------------------------------
// GraphConvolution: out[dst] += w_e * (X @ W)[src]
// R13: exact R9 + single change: 3-kernel scan -> 1-kernel decoupled-lookback
//      scan (self-cleaning state). Edge branch: memset, hist, scan_lb, place.
// ---------------------------------------------------------------------------

#define N_NODES_MAX 100000
#define E_MAX       1600000
#define IN_F  256
#define OUT_F 128

__device__ __half g_support[(size_t)N_NODES_MAX * OUT_F];
__device__ int    g_count[N_NODES_MAX];
__device__ int    g_offsets[N_NODES_MAX];
__device__ int    g_cursor[N_NODES_MAX];
__device__ uint2  g_edges[E_MAX];                  // (src, w bits), dst-bucketed
__device__ unsigned long long g_lb[64];            // lookback state (self-clean)
__device__ int    g_lb_done;                       // (self-clean)

// int64 edge_index <=> odd 32-bit words of the first 32 values are all zero
__device__ __forceinline__ int block_is64(const unsigned int* raw, int* sh)
{
    if (threadIdx.x == 0) {
        int is64 = 1;
        #pragma unroll
        for (int k = 1; k < 64; k += 2)
            if (raw[k] != 0u) { is64 = 0; break; }
        *sh = is64;
    }
    __syncthreads();
    return *sh;
}

// ---------------- histogram over dst ------------------------------------------
__global__ void hist_kernel(const unsigned int* __restrict__ raw, int E)
{
    __shared__ int sh_is64;
    const int is64 = block_is64(raw, &sh_is64);
    int e = blockIdx.x * blockDim.x + threadIdx.x;
    if (e >= E) return;
    int d = is64 ? (int)((const long long*)raw)[e] : ((const int*)raw)[e];
    atomicAdd(&g_count[d], 1);
}

// ---------------- single-pass decoupled-lookback exclusive scan ----------------
// 1024 threads x 4 items = 4096/block; M=100000 -> 25 blocks (< 32: one window).
__global__ __launch_bounds__(1024) void scan_lb_kernel(int M)
{
    __shared__ int ws[32];
    __shared__ int s_excl;
    const int t    = threadIdx.x;
    const int lane = t & 31;
    const int wid  = t >> 5;
    const int bid  = blockIdx.x;
    const int base = bid * 4096 + t * 4;

    // load 4 items
    int v[4];
    if (base + 3 < M) {
        int4 lv = *reinterpret_cast<const int4*>(g_count + base);
        v[0] = lv.x; v[1] = lv.y; v[2] = lv.z; v[3] = lv.w;
    } else {
        #pragma unroll
        for (int q = 0; q < 4; q++) v[q] = (base + q < M) ? g_count[base + q] : 0;
    }
    const int tsum = v[0] + v[1] + v[2] + v[3];

    // warp inclusive scan of per-thread sums
    int incl = tsum;
    #pragma unroll
    for (int off = 1; off < 32; off <<= 1) {
        int x = __shfl_up_sync(0xffffffffu, incl, off);
        if (lane >= off) incl += x;
    }
    if (lane == 31) ws[wid] = incl;
    __syncthreads();
    if (wid == 0) {
        int s = ws[lane];
        #pragma unroll
        for (int off = 1; off < 32; off <<= 1) {
            int x = __shfl_up_sync(0xffffffffu, s, off);
            if (lane >= off) s += x;
        }
        ws[lane] = s;
    }
    __syncthreads();
    const int warpoff = (wid == 0) ? 0 : ws[wid - 1];
    const int texcl   = warpoff + incl - tsum;     // thread-exclusive in block
    const int btotal  = ws[31];

    // publish + lookback
    if (bid == 0) {
        if (t == 0) {
            atomicExch(&g_lb[0], (2ULL << 32) | (unsigned)btotal);
            s_excl = 0;
        }
    } else if (wid == 0) {
        if (lane == 0)
            atomicExch(&g_lb[bid], (1ULL << 32) | (unsigned)btotal);
        const int idx = bid - 1 - lane;            // may be negative
        int excl = 0;
        for (;;) {
            unsigned long long e = (idx >= 0)
                ? atomicAdd(&g_lb[idx], 0ULL)      // volatile device-scope read
                : (2ULL << 32);                    // sentinel: inclusive 0
            const unsigned st = (unsigned)(e >> 32);
            const unsigned bal_pub = __ballot_sync(0xffffffffu, st >= 1u);
            const unsigned bal_inc = __ballot_sync(0xffffffffu, st == 2u);
            if (bal_inc) {
                const int lstar = __ffs(bal_inc) - 1;   // nearest inclusive pred
                const unsigned need = (lstar > 0) ? ((1u << lstar) - 1u) : 0u;
                if ((bal_pub & need) == need) {
                    int c = (lane <= lstar) ? (int)(unsigned)e : 0;
                    #pragma unroll
                    for (int off = 16; off >= 1; off >>= 1)
                        c += __shfl_xor_sync(0xffffffffu, c, off);
                    excl = c;
                    break;
                }
            }
        }
        if (lane == 0) {
            atomicExch(&g_lb[bid], (2ULL << 32) | (unsigned)(excl + btotal));
            s_excl = excl;
        }
    }
    __syncthreads();

    // write exclusive offsets + cursor
    int ex = s_excl + texcl;
    #pragma unroll
    for (int q = 0; q < 4; q++) {
        if (base + q < M) { g_offsets[base + q] = ex; g_cursor[base + q] = ex; }
        ex += v[q];
    }

    // self-clean: last block to finish zeroes the state for the next replay
    __syncthreads();
    if (t == 0) {
        __threadfence();
        int d = atomicAdd(&g_lb_done, 1);
        if (d == gridDim.x - 1) {
            for (int i = 0; i < gridDim.x; i++) g_lb[i] = 0ULL;
            g_lb_done = 0;
            __threadfence();
        }
    }
}

// ---------------- place edges into dst buckets --------------------------------
__global__ void place_kernel(const unsigned int* __restrict__ raw,
                             const float* __restrict__ ew, int E)
{
    __shared__ int sh_is64;
    const int is64 = block_is64(raw, &sh_is64);
    int e = blockIdx.x * blockDim.x + threadIdx.x;
    if (e >= E) return;
    int d, s;
    if (is64) {
        const long long* ei = (const long long*)raw;
        d = (int)ei[e]; s = (int)ei[(size_t)E + e];
    } else {
        const int* ei = (const int*)raw;
        d = ei[e]; s = ei[(size_t)E + e];
    }
    int pos = atomicAdd(&g_cursor[d], 1);
    g_edges[pos] = make_uint2((unsigned)s, __float_as_uint(ew[e]));
}

// ---------------- fp16 mma helper ---------------------------------------------
__device__ __forceinline__ void mma_f16(
    float& c0, float& c1, float& c2, float& c3,
    uint32_t a0, uint32_t a1, uint32_t a2, uint32_t a3,
    uint32_t b0, uint32_t b1)
{
    asm volatile(
        "mma.sync.aligned.m16n8k16.row.col.f32.f16.f16.f32 "
        "{%0,%1,%2,%3}, {%4,%5,%6,%7}, {%8,%9}, {%0,%1,%2,%3};"
        : "+f"(c0), "+f"(c1), "+f"(c2), "+f"(c3)
        : "r"(a0), "r"(a1), "r"(a2), "r"(a3), "r"(b0), "r"(b1));
}

// ---------------- GEMM 128x128 CTA tile, fp16 mma, fp32 accum -----------------
#define KC 64                 // k-chunk (halves)
#define PADH 72               // smem row stride in halves

__global__ __launch_bounds__(256) void gemm_mma_kernel(
    const float* __restrict__ X, const float* __restrict__ W,
    __half* __restrict__ S, int M)
{
    __shared__ __half As[128][PADH];
    __shared__ __half Bs[128][PADH];

    const int t    = threadIdx.x;
    const int w    = t >> 5;
    const int lane = t & 31;
    const int g    = lane >> 2;
    const int tig  = lane & 3;
    const int wm   = (w & 3) * 32;
    const int wn   = (w >> 2) * 64;
    const int m0   = blockIdx.x * 128;

    float acc[2][8][4];
    #pragma unroll
    for (int mi = 0; mi < 2; mi++)
        #pragma unroll
        for (int ni = 0; ni < 8; ni++)
            #pragma unroll
            for (int r = 0; r < 4; r++) acc[mi][ni][r] = 0.0f;

    for (int k0 = 0; k0 < IN_F; k0 += KC) {
        #pragma unroll
        for (int i = 0; i < 8; i++) {
            int idx = t + i * 256;
            int r   = idx >> 4;
            int c   = (idx & 15) * 4;
            float4 v = make_float4(0.f, 0.f, 0.f, 0.f);
            if (m0 + r < M)
                v = *reinterpret_cast<const float4*>(
                        X + (size_t)(m0 + r) * IN_F + k0 + c);
            *reinterpret_cast<__half2*>(&As[r][c])     = __floats2half2_rn(v.x, v.y);
            *reinterpret_cast<__half2*>(&As[r][c + 2]) = __floats2half2_rn(v.z, v.w);
        }
        #pragma unroll
        for (int i = 0; i < 32; i++) {
            int idx = t + i * 256;
            int k   = idx >> 7;
            int n   = idx & 127;
            Bs[n][k] = __float2half_rn(W[(size_t)(k0 + k) * OUT_F + n]);
        }
        __syncthreads();

        #pragma unroll
        for (int ks = 0; ks < KC / 16; ks++) {
            const int k = ks * 16;
            uint32_t a[2][4];
            #pragma unroll
            for (int mi = 0; mi < 2; mi++) {
                int mr = wm + mi * 16 + g;
                a[mi][0] = *reinterpret_cast<const uint32_t*>(&As[mr    ][k + tig * 2]);
                a[mi][1] = *reinterpret_cast<const uint32_t*>(&As[mr + 8][k + tig * 2]);
                a[mi][2] = *reinterpret_cast<const uint32_t*>(&As[mr    ][k + 8 + tig * 2]);
                a[mi][3] = *reinterpret_cast<const uint32_t*>(&As[mr + 8][k + 8 + tig * 2]);
            }
            uint32_t b[8][2];
            #pragma unroll
            for (int ni = 0; ni < 8; ni++) {
                int nr = wn + ni * 8 + g;
                b[ni][0] = *reinterpret_cast<const uint32_t*>(&Bs[nr][k + tig * 2]);
                b[ni][1] = *reinterpret_cast<const uint32_t*>(&Bs[nr][k + 8 + tig * 2]);
            }
            #pragma unroll
            for (int mi = 0; mi < 2; mi++)
                #pragma unroll
                for (int ni = 0; ni < 8; ni++)
                    mma_f16(acc[mi][ni][0], acc[mi][ni][1],
                            acc[mi][ni][2], acc[mi][ni][3],
                            a[mi][0], a[mi][1], a[mi][2], a[mi][3],
                            b[ni][0], b[ni][1]);
        }
        __syncthreads();
    }

    #pragma unroll
    for (int mi = 0; mi < 2; mi++) {
        int r0 = m0 + wm + mi * 16 + g;
        #pragma unroll
        for (int ni = 0; ni < 8; ni++) {
            int c = wn + ni * 8 + tig * 2;
            if (r0 < M)
                *reinterpret_cast<__half2*>(S + (size_t)r0 * OUT_F + c) =
                    __floats2half2_rn(acc[mi][ni][0], acc[mi][ni][1]);
            if (r0 + 8 < M)
                *reinterpret_cast<__half2*>(S + (size_t)(r0 + 8) * OUT_F + c) =
                    __floats2half2_rn(acc[mi][ni][2], acc[mi][ni][3]);
        }
    }
}

// ---------------- warp-per-node aggregation (R9 proven inner loop) ------------
__global__ __launch_bounds__(256) void aggregate_kernel(
    const __half* __restrict__ S, float* __restrict__ out, int M)
{
    const int node = (blockIdx.x * blockDim.x + threadIdx.x) >> 5;
    const int lane = threadIdx.x & 31;
    if (node >= M) return;

    const int start = g_offsets[node];
    const int cnt   = g_count[node];

    float4 acc0 = make_float4(0.f, 0.f, 0.f, 0.f);
    float4 acc1 = make_float4(0.f, 0.f, 0.f, 0.f);

    for (int b = 0; b < cnt; b += 32) {
        const int nb = (cnt - b < 32) ? (cnt - b) : 32;
        uint2 p = make_uint2(0u, 0u);
        if (lane < nb) p = g_edges[start + b + lane];

        int j = 0;
        for (; j + 4 <= nb; j += 4) {
            unsigned s0 = __shfl_sync(0xffffffffu, p.x, j);
            unsigned s1 = __shfl_sync(0xffffffffu, p.x, j + 1);
            unsigned s2 = __shfl_sync(0xffffffffu, p.x, j + 2);
            unsigned s3 = __shfl_sync(0xffffffffu, p.x, j + 3);
            float w0 = __uint_as_float(__shfl_sync(0xffffffffu, p.y, j));
            float w1 = __uint_as_float(__shfl_sync(0xffffffffu, p.y, j + 1));
            float w2 = __uint_as_float(__shfl_sync(0xffffffffu, p.y, j + 2));
            float w3 = __uint_as_float(__shfl_sync(0xffffffffu, p.y, j + 3));

            uint2 r0 = *reinterpret_cast<const uint2*>(S + (size_t)s0 * OUT_F + lane * 4);
            uint2 r1 = *reinterpret_cast<const uint2*>(S + (size_t)s1 * OUT_F + lane * 4);
            uint2 r2 = *reinterpret_cast<const uint2*>(S + (size_t)s2 * OUT_F + lane * 4);
            uint2 r3 = *reinterpret_cast<const uint2*>(S + (size_t)s3 * OUT_F + lane * 4);

            float2 a, bb;
            a  = __half22float2(*reinterpret_cast<__half2*>(&r0.x));
            bb = __half22float2(*reinterpret_cast<__half2*>(&r0.y));
            acc0.x = fmaf(w0, a.x,  acc0.x); acc0.y = fmaf(w0, a.y,  acc0.y);
            acc0.z = fmaf(w0, bb.x, acc0.z); acc0.w = fmaf(w0, bb.y, acc0.w);
            a  = __half22float2(*reinterpret_cast<__half2*>(&r1.x));
            bb = __half22float2(*reinterpret_cast<__half2*>(&r1.y));
            acc1.x = fmaf(w1, a.x,  acc1.x); acc1.y = fmaf(w1, a.y,  acc1.y);
            acc1.z = fmaf(w1, bb.x, acc1.z); acc1.w = fmaf(w1, bb.y, acc1.w);
            a  = __half22float2(*reinterpret_cast<__half2*>(&r2.x));
            bb = __half22float2(*reinterpret_cast<__half2*>(&r2.y));
            acc0.x = fmaf(w2, a.x,  acc0.x); acc0.y = fmaf(w2, a.y,  acc0.y);
            acc0.z = fmaf(w2, bb.x, acc0.z); acc0.w = fmaf(w2, bb.y, acc0.w);
            a  = __half22float2(*reinterpret_cast<__half2*>(&r3.x));
            bb = __half22float2(*reinterpret_cast<__half2*>(&r3.y));
            acc1.x = fmaf(w3, a.x,  acc1.x); acc1.y = fmaf(w3, a.y,  acc1.y);
            acc1.z = fmaf(w3, bb.x, acc1.z); acc1.w = fmaf(w3, bb.y, acc1.w);
        }
        for (; j < nb; j++) {
            unsigned sj = __shfl_sync(0xffffffffu, p.x, j);
            float    wj = __uint_as_float(__shfl_sync(0xffffffffu, p.y, j));
            uint2 r = *reinterpret_cast<const uint2*>(S + (size_t)sj * OUT_F + lane * 4);
            float2 a  = __half22float2(*reinterpret_cast<__half2*>(&r.x));
            float2 bb = __half22float2(*reinterpret_cast<__half2*>(&r.y));
            acc0.x = fmaf(wj, a.x,  acc0.x); acc0.y = fmaf(wj, a.y,  acc0.y);
            acc0.z = fmaf(wj, bb.x, acc0.z); acc0.w = fmaf(wj, bb.y, acc0.w);
        }
    }
    float4 r = make_float4(acc0.x + acc1.x, acc0.y + acc1.y,
                           acc0.z + acc1.z, acc0.w + acc1.w);
    *reinterpret_cast<float4*>(out + (size_t)node * OUT_F + lane * 4) = r;
}

// ---------------------------------------------------------------------------
extern "C" void kernel_launch(void* const* d_in, const int* in_sizes, int n_in,
                              void* d_out, int out_size)
{
    const float*        X  = (const float*)d_in[0];
    const unsigned int* EI = (const unsigned int*)d_in[1];
    const float*        EW = (const float*)d_in[2];
    const float*        W  = (const float*)d_in[3];
    float*              O  = (float*)d_out;

    const int M = out_size / OUT_F;
    const int E = in_sizes[2];

    __half* S;  cudaGetSymbolAddress((void**)&S, g_support);
    int*   CNT; cudaGetSymbolAddress((void**)&CNT, g_count);

    const int nbScan = (M + 4095) / 4096;

    cudaStream_t s2;
    cudaStreamCreateWithFlags(&s2, cudaStreamNonBlocking);
    cudaEvent_t evFork, evJoin;
    cudaEventCreateWithFlags(&evFork, cudaEventDisableTiming);
    cudaEventCreateWithFlags(&evJoin, cudaEventDisableTiming);

    cudaEventRecord(evFork, 0);
    cudaStreamWaitEvent(s2, evFork, 0);

    // --- branch B (s2): edge bucketing (memset + 3 kernels) ---
    cudaMemsetAsync(CNT, 0, (size_t)M * sizeof(int), s2);
    hist_kernel<<<(E + 255) / 256, 256, 0, s2>>>(EI, E);
    scan_lb_kernel<<<nbScan, 1024, 0, s2>>>(M);
    place_kernel<<<(E + 255) / 256, 256, 0, s2>>>(EI, EW, E);
    cudaEventRecord(evJoin, s2);

    // --- branch A (default stream): GEMM ---
    gemm_mma_kernel<<<(M + 127) / 128, 256>>>(X, W, S, M);

    // --- join, then aggregate ---
    cudaStreamWaitEvent(0, evJoin, 0);
    aggregate_kernel<<<(M * 32 + 255) / 256, 256>>>(S, O, M);

    cudaStreamDestroy(s2);
    cudaEventDestroy(evFork);
    cudaEventDestroy(evJoin);
}